// round 10
// baseline (speedup 1.0000x reference)
#include <cuda_runtime.h>
#include <cuda_bf16.h>
#include <math.h>

#define NMAX 100000
#define EMAX 1600000
#define HID 128
#define NCLS 40
#define NEG_SLOPE 0.2f
#define BN_EPS 1e-5f

// ---------------- device scratch (no allocations allowed) ----------------
__device__ float g_bufA[NMAX * HID];     // h after GEMM
__device__ float g_bufB[NMAX * HID];     // aggregation output
__device__ float g_esrc[NMAX];
__device__ float g_edst[NMAX];
__device__ int   g_deg[NMAX];            // dst in-degree (incl self)
__device__ int   g_sdeg[NMAX];           // src out-degree (incl self)
__device__ int   g_rowptr[NMAX + 1];     // dst CSR
__device__ int   g_srowptr[NMAX + 1];    // src CSR
__device__ int   g_cursor[NMAX];
__device__ int   g_scursor[NMAX];
__device__ int   g_csrc[EMAX + NMAX];    // dst-slot -> src node
__device__ int   g_p2q[EMAX + NMAX];     // dst-slot -> src-slot
__device__ int   g_sdst[EMAX + NMAX];    // src-slot -> dst node
__device__ float g_alphas[EMAX + NMAX];  // alpha in SRC-slot order
__device__ float g_bn_sum[HID];
__device__ float g_bn_sq[HID];
__device__ float g_bn_scale[HID];
__device__ float g_bn_shift[HID];
__device__ int   g_is64;
__device__ unsigned g_gbar;   // monotone grid-barrier counter (never reset)

__device__ __forceinline__ int edge_at(const void* ei, long long idx, int is64) {
    if (is64) return (int)((const long long*)ei)[idx];
    return ((const int*)ei)[idx];
}

// ---------------- fused dual-CSR build: one kernel, software grid barrier --
#define CSR_NB 128
#define CSR_NPH 3

__device__ __forceinline__ void gridbar(unsigned* s_base, int phase) {
    __syncthreads();
    if (threadIdx.x == 0) {
        __threadfence();
        unsigned c = atomicAdd(&g_gbar, 1u);
        if (phase == 1)
            *s_base = (c / (CSR_NB * CSR_NPH)) * (CSR_NB * CSR_NPH);
        unsigned target = *s_base + (unsigned)phase * CSR_NB;
        volatile unsigned* p = &g_gbar;
        while (*p < target) { __nanosleep(32); }
        __threadfence();
    }
    __syncthreads();
}

__global__ __launch_bounds__(1024) void k_csr(const void* ei, int E, int n) {
    __shared__ unsigned s_base;
    __shared__ int part[1024];
    int tid = threadIdx.x;
    int gid = blockIdx.x * 1024 + tid;
    int gsz = CSR_NB * 1024;

    // phase 0: dtype detect + degree init (self-loop = 1) + BN accumulator zero
    if (blockIdx.x == 0 && tid == 0) {
        const long long* p = (const long long*)ei;
        int cnt = (E < 64) ? E : 64;
        int ok = 1;
        for (int q = 0; q < cnt; q++) {
            long long v = p[q];
            if (v < 0 || v >= n) { ok = 0; break; }
        }
        g_is64 = ok;
    }
    if (blockIdx.x == 0 && tid < HID) { g_bn_sum[tid] = 0.f; g_bn_sq[tid] = 0.f; }
    for (int i = gid; i < n; i += gsz) { g_deg[i] = 1; g_sdeg[i] = 1; }

    gridbar(&s_base, 1);

    // phase 1: degree counts (both directions)
    int is64 = g_is64;
    for (int e = gid; e < E; e += gsz) {
        int s = edge_at(ei, e, is64);
        int d = edge_at(ei, (long long)E + e, is64);
        atomicAdd(&g_deg[d], 1);
        atomicAdd(&g_sdeg[s], 1);
    }

    gridbar(&s_base, 2);

    // phase 2: exclusive scans (block 0: dst, block 1: src)
    if (blockIdx.x < 2) {
        const int* dv = (blockIdx.x == 0) ? g_deg : g_sdeg;
        int* rp = (blockIdx.x == 0) ? g_rowptr : g_srowptr;
        int* cu = (blockIdx.x == 0) ? g_cursor : g_scursor;
        int c = (n + 1023) >> 10;
        int lo = tid * c;
        int hi = lo + c; if (hi > n) hi = n; if (lo > n) lo = n;
        int s = 0;
        for (int i = lo; i < hi; i++) s += dv[i];
        part[tid] = s;
        __syncthreads();
        for (int off = 1; off < 1024; off <<= 1) {
            int v = (tid >= off) ? part[tid - off] : 0;
            __syncthreads();
            part[tid] += v;
            __syncthreads();
        }
        int run = (tid > 0) ? part[tid - 1] : 0;
        for (int i = lo; i < hi; i++) {
            rp[i] = run;
            cu[i] = run;
            run += dv[i];
        }
        if (tid == 1023) rp[n] = part[1023];
    }

    gridbar(&s_base, 3);

    // phase 3: fill both CSRs + permutation
    int total = E + n;
    for (int e = gid; e < total; e += gsz) {
        int s, d;
        if (e < E) {
            s = edge_at(ei, e, is64);
            d = edge_at(ei, (long long)E + e, is64);
        } else {
            s = d = e - E;
        }
        int p = atomicAdd(&g_cursor[d], 1);
        int q = atomicAdd(&g_scursor[s], 1);
        g_csrc[p] = s;
        g_sdst[q] = d;
        g_p2q[p] = q;
    }
}

// ------ SGEMM + fused attention scores: C = f(A)*B; esrc/edst from C -------
template <bool TRANSFORM>
__global__ __launch_bounds__(256) void k_gemm128(const float* __restrict__ A,
                                                 const float* __restrict__ B,
                                                 float* __restrict__ C,
                                                 const float* __restrict__ a_s,
                                                 const float* __restrict__ a_d,
                                                 int n) {
    __shared__ float As[16][128];  // [k][m]
    __shared__ float Bs[16][128];  // [k][col]
    int tid = threadIdx.x;
    int tx = tid & 15, ty = tid >> 4;
    int row0 = blockIdx.x * 128;

    float acc[8][8];
#pragma unroll
    for (int i = 0; i < 8; i++)
#pragma unroll
        for (int j = 0; j < 8; j++) acc[i][j] = 0.f;

    for (int k0 = 0; k0 < 128; k0 += 16) {
#pragma unroll
        for (int q = 0; q < 2; q++) {
            int i = tid * 2 + q;
            int m = i >> 2;
            int kq = i & 3;
            int row = row0 + m;
            float4 v = make_float4(0.f, 0.f, 0.f, 0.f);
            if (row < n) v = ((const float4*)A)[(long long)row * 32 + (k0 >> 2) + kq];
            if (TRANSFORM) {
                float4 sc = ((const float4*)g_bn_scale)[(k0 >> 2) + kq];
                float4 sh = ((const float4*)g_bn_shift)[(k0 >> 2) + kq];
                float t;
                t = v.x * sc.x + sh.x; v.x = (t > 0.f) ? t : expm1f(t);
                t = v.y * sc.y + sh.y; v.y = (t > 0.f) ? t : expm1f(t);
                t = v.z * sc.z + sh.z; v.z = (t > 0.f) ? t : expm1f(t);
                t = v.w * sc.w + sh.w; v.w = (t > 0.f) ? t : expm1f(t);
            }
            As[kq * 4 + 0][m] = v.x;
            As[kq * 4 + 1][m] = v.y;
            As[kq * 4 + 2][m] = v.z;
            As[kq * 4 + 3][m] = v.w;
        }
#pragma unroll
        for (int q = 0; q < 2; q++) {
            int i = tid * 2 + q;
            int kk = i >> 5;
            int c4 = i & 31;
            ((float4*)Bs[kk])[c4] = ((const float4*)B)[(k0 + kk) * 32 + c4];
        }
        __syncthreads();
#pragma unroll
        for (int kk = 0; kk < 16; kk++) {
            float a[8], b[8];
            *(float4*)(a)     = *(const float4*)&As[kk][ty * 8];
            *(float4*)(a + 4) = *(const float4*)&As[kk][ty * 8 + 4];
            *(float4*)(b)     = *(const float4*)&Bs[kk][tx * 8];
            *(float4*)(b + 4) = *(const float4*)&Bs[kk][tx * 8 + 4];
#pragma unroll
            for (int i = 0; i < 8; i++)
#pragma unroll
                for (int j = 0; j < 8; j++) acc[i][j] += a[i] * b[j];
        }
        __syncthreads();
    }
    // write C
#pragma unroll
    for (int i = 0; i < 8; i++) {
        int row = row0 + ty * 8 + i;
        if (row < n) {
            float4 v0 = make_float4(acc[i][0], acc[i][1], acc[i][2], acc[i][3]);
            float4 v1 = make_float4(acc[i][4], acc[i][5], acc[i][6], acc[i][7]);
            ((float4*)C)[(long long)row * 32 + tx * 2]     = v0;
            ((float4*)C)[(long long)row * 32 + tx * 2 + 1] = v1;
        }
    }
    // fused attention scores
    float as_[8], ad_[8];
    *(float4*)(as_)     = ((const float4*)a_s)[tx * 2];
    *(float4*)(as_ + 4) = ((const float4*)a_s)[tx * 2 + 1];
    *(float4*)(ad_)     = ((const float4*)a_d)[tx * 2];
    *(float4*)(ad_ + 4) = ((const float4*)a_d)[tx * 2 + 1];
#pragma unroll
    for (int i = 0; i < 8; i++) {
        float ps = 0.f, pd = 0.f;
#pragma unroll
        for (int j = 0; j < 8; j++) { ps += acc[i][j] * as_[j]; pd += acc[i][j] * ad_[j]; }
#pragma unroll
        for (int o = 8; o; o >>= 1) {
            ps += __shfl_xor_sync(0xffffffffu, ps, o);
            pd += __shfl_xor_sync(0xffffffffu, pd, o);
        }
        int row = row0 + ty * 8 + i;
        if (tx == 0 && row < n) { g_esrc[row] = ps; g_edst[row] = pd; }
    }
}

// -- per-node softmax -> alpha scattered to SRC order; also out=bias init ---
__global__ __launch_bounds__(256) void k_alpha(float* __restrict__ out,
                                               const float* __restrict__ bias,
                                               int n) {
    // init out = bias (grid-stride float4)
    long long total4 = (long long)n * 32;
    for (long long i = (long long)blockIdx.x * 256 + threadIdx.x; i < total4;
         i += (long long)gridDim.x * 256)
        ((float4*)out)[i] = ((const float4*)bias)[(int)(i & 31)];

    int gid = blockIdx.x * blockDim.x + threadIdx.x;
    int w = gid >> 5, lane = gid & 31;
    if (w >= n) return;
    int b0 = g_rowptr[w], b1 = g_rowptr[w + 1];
    float ed = g_edst[w];

    float m = -1e30f;
    for (int j = b0 + lane; j < b1; j += 32) {
        float t = g_esrc[g_csrc[j]] + ed;
        float e = (t > 0.f) ? t : NEG_SLOPE * t;
        m = fmaxf(m, e);
    }
#pragma unroll
    for (int o = 16; o; o >>= 1) m = fmaxf(m, __shfl_xor_sync(0xffffffffu, m, o));

    float dl = 0.f;
    for (int j = b0 + lane; j < b1; j += 32) {
        float t = g_esrc[g_csrc[j]] + ed;
        float e = (t > 0.f) ? t : NEG_SLOPE * t;
        dl += __expf(e - m);
    }
#pragma unroll
    for (int o = 16; o; o >>= 1) dl += __shfl_xor_sync(0xffffffffu, dl, o);
    float inv = 1.0f / dl;

    for (int j = b0 + lane; j < b1; j += 32) {
        float t = g_esrc[g_csrc[j]] + ed;
        float e = (t > 0.f) ? t : NEG_SLOPE * t;
        g_alphas[g_p2q[j]] = __expf(e - m) * inv;   // random 4B write (fast)
    }
}

// ---- src-major scatter: sequential reads, coalesced atomic RED writes -----
#define SCAT_NB 2048
__global__ __launch_bounds__(256) void k_scatter(const float* __restrict__ h,
                                                 float* __restrict__ out, int n) {
    int f = threadIdx.x & 127;
    int sub = threadIdx.x >> 7;
    for (int s = blockIdx.x * 2 + sub; s < n; s += SCAT_NB * 2) {
        float hv = h[(long long)s * HID + f];
        int q0 = g_srowptr[s], q1 = g_srowptr[s + 1];
        int j = q0;
        for (; j + 4 <= q1; j += 4) {
            int   d0 = g_sdst[j],     d1 = g_sdst[j + 1];
            int   d2 = g_sdst[j + 2], d3 = g_sdst[j + 3];
            float a0 = g_alphas[j],     a1 = g_alphas[j + 1];
            float a2 = g_alphas[j + 2], a3 = g_alphas[j + 3];
            atomicAdd(&out[(long long)d0 * HID + f], a0 * hv);
            atomicAdd(&out[(long long)d1 * HID + f], a1 * hv);
            atomicAdd(&out[(long long)d2 * HID + f], a2 * hv);
            atomicAdd(&out[(long long)d3 * HID + f], a3 * hv);
        }
        for (; j < q1; j++)
            atomicAdd(&out[(long long)g_sdst[j] * HID + f], g_alphas[j] * hv);
    }
}

// ---------------- BN stats: streaming pass over aggregated output ----------
__global__ void k_bn_stats(const float* __restrict__ z, int n) {
    int f = threadIdx.x;  // 128 threads
    float s = 0.f, q = 0.f;
    for (int r = blockIdx.x; r < n; r += gridDim.x) {
        float v = z[(long long)r * HID + f];
        s += v; q += v * v;
    }
    atomicAdd(&g_bn_sum[f], s);
    atomicAdd(&g_bn_sq[f], q);
}

// -------- BN finalize: scale/shift; resets accumulators for next layer -----
__global__ void k_bn_final(const float* __restrict__ gamma, const float* __restrict__ beta,
                           float inv_n) {
    int f = threadIdx.x;
    if (f < HID) {
        float mu = g_bn_sum[f] * inv_n;
        float var = g_bn_sq[f] * inv_n - mu * mu;
        float rstd = rsqrtf(var + BN_EPS);
        float sc = rstd * gamma[f];
        g_bn_scale[f] = sc;
        g_bn_shift[f] = beta[f] - mu * sc;
        g_bn_sum[f] = 0.f;
        g_bn_sq[f] = 0.f;
    }
}

// ---------------- output GEMM: elu(bn(h)) @ [128 x 40] + bias --------------
__global__ __launch_bounds__(256) void k_outgemm(const float* __restrict__ h,
                                                 const float* __restrict__ Wout,
                                                 const float* __restrict__ bout,
                                                 float* __restrict__ out, int n) {
    __shared__ float hs[32][129];
    __shared__ float ws[128 * NCLS];
    int r0 = blockIdx.x * 32;
    for (int i = threadIdx.x; i < 128 * NCLS; i += 256) ws[i] = Wout[i];
    for (int i = threadIdx.x; i < 32 * 128; i += 256) {
        int r = i >> 7, k = i & 127;
        float v = (r0 + r < n) ? h[(long long)(r0 + r) * 128 + k] : 0.f;
        float t = v * g_bn_scale[k] + g_bn_shift[k];
        hs[r][k] = (t > 0.f) ? t : expm1f(t);
    }
    __syncthreads();
    int r = threadIdx.x >> 3;
    int cg = threadIdx.x & 7;
    float acc[5] = {0.f, 0.f, 0.f, 0.f, 0.f};
    for (int k = 0; k < 128; k++) {
        float a = hs[r][k];
#pragma unroll
        for (int j = 0; j < 5; j++) acc[j] += a * ws[k * NCLS + cg * 5 + j];
    }
    int row = r0 + r;
    if (row < n) {
#pragma unroll
        for (int j = 0; j < 5; j++)
            out[(long long)row * NCLS + cg * 5 + j] = acc[j] + bout[cg * 5 + j];
    }
}

// ---------------- launch ----------------
extern "C" void kernel_launch(void* const* d_in, const int* in_sizes, int n_in,
                              void* d_out, int out_size) {
    const float* x    = (const float*)d_in[0];
    const void*  ei   = d_in[1];
    const float* W1   = (const float*)d_in[2];
    const float* as1  = (const float*)d_in[3];
    const float* ad1  = (const float*)d_in[4];
    const float* b1   = (const float*)d_in[5];
    const float* W2   = (const float*)d_in[6];
    const float* as2  = (const float*)d_in[7];
    const float* ad2  = (const float*)d_in[8];
    const float* b2   = (const float*)d_in[9];
    const float* gamma= (const float*)d_in[10];
    const float* beta = (const float*)d_in[11];
    const float* Wout = (const float*)d_in[12];
    const float* bout = (const float*)d_in[13];
    float* out = (float*)d_out;

    int n = in_sizes[0] / HID;       // 100000
    int E = in_sizes[1] / 2;         // 1600000
    float inv_n = 1.0f / (float)n;

    int gemm_blocks = (n + 127) / 128;
    int warp_blocks = (n + 7) / 8;

    // launch order (ncu profiles idx 3 -> k_scatter):
    k_csr<<<CSR_NB, 1024>>>(ei, E, n);                                      // 0
    k_gemm128<false><<<gemm_blocks, 256>>>(x, W1, g_bufA, as1, ad1, n);     // 1
    k_alpha<<<warp_blocks, 256>>>(g_bufB, b1, n);                           // 2
    k_scatter<<<SCAT_NB, 256>>>(g_bufA, g_bufB, n);                         // 3 <- ncu
    k_bn_stats<<<512, HID>>>(g_bufB, n);                                    // 4
    k_bn_final<<<1, HID>>>(gamma, beta, inv_n);                             // 5

    // --- layer 2 (BN+ELU fused into A-load of GEMM) ---
    k_gemm128<true><<<gemm_blocks, 256>>>(g_bufB, W2, g_bufA, as2, ad2, n); // 6
    k_alpha<<<warp_blocks, 256>>>(g_bufB, b2, n);                           // 7
    k_scatter<<<SCAT_NB, 256>>>(g_bufA, g_bufB, n);                         // 8
    k_bn_stats<<<512, HID>>>(g_bufB, n);                                    // 9
    k_bn_final<<<1, HID>>>(gamma, beta, inv_n);                             // 10

    // --- output projection (BN+ELU fused into h-load) ---
    k_outgemm<<<(n + 31) / 32, 256>>>(g_bufB, Wout, bout, out, n);          // 11
}

// round 12
// speedup vs baseline: 14.4684x; 14.4684x over previous
#include <cuda_runtime.h>
#include <cuda_fp16.h>
#include <math.h>

#define NMAX 100000
#define EMAX 1600000
#define HID 128
#define NCLS 40
#define NEG_SLOPE 0.2f
#define BN_EPS 1e-5f

// ---------------- device scratch (no allocations allowed) ----------------
__device__ unsigned g_hpk[NMAX * 64];    // feature table, fp16x2 packed (25.6MB)
__device__ float g_bufB[NMAX * HID];     // aggregation output (fp32)
__device__ float g_esrc[NMAX];
__device__ float g_edst[NMAX];
__device__ int   g_deg[NMAX];
__device__ int   g_rowptr[NMAX + 1];
__device__ int   g_cursor[NMAX];
__device__ int   g_csrc[EMAX + NMAX];
__device__ float g_alpha[EMAX + NMAX];
__device__ float g_bn_sum[HID];
__device__ float g_bn_sq[HID];
__device__ float g_bn_scale[HID];
__device__ float g_bn_shift[HID];
__device__ int   g_is64;
__device__ unsigned g_gbar;   // monotone grid-barrier counter (never reset)

__device__ __forceinline__ int edge_at(const void* ei, long long idx, int is64) {
    if (is64) return (int)((const long long*)ei)[idx];
    return ((const int*)ei)[idx];
}

__device__ __forceinline__ unsigned pk_h2(float a, float b) {
    __half2 t = __float22half2_rn(make_float2(a, b));
    return *(unsigned*)&t;
}

// ---------------- fused CSR build: one kernel, software grid barrier -------
#define CSR_NB 128
#define CSR_NPH 3

__device__ __forceinline__ void gridbar(unsigned* s_base, int phase) {
    __syncthreads();
    if (threadIdx.x == 0) {
        __threadfence();
        unsigned c = atomicAdd(&g_gbar, 1u);
        if (phase == 1)
            *s_base = (c / (CSR_NB * CSR_NPH)) * (CSR_NB * CSR_NPH);
        unsigned target = *s_base + (unsigned)phase * CSR_NB;
        volatile unsigned* p = &g_gbar;
        while (*p < target) { __nanosleep(32); }
        __threadfence();
    }
    __syncthreads();
}

__global__ __launch_bounds__(1024) void k_csr(const void* ei, int E, int n) {
    __shared__ unsigned s_base;
    __shared__ int part[1024];
    int tid = threadIdx.x;
    int gid = blockIdx.x * 1024 + tid;
    int gsz = CSR_NB * 1024;

    // phase 0: dtype detect + degree init (self-loop = 1) + BN accumulator zero
    if (blockIdx.x == 0 && tid == 0) {
        const long long* p = (const long long*)ei;
        int cnt = (E < 64) ? E : 64;
        int ok = 1;
        for (int q = 0; q < cnt; q++) {
            long long v = p[q];
            if (v < 0 || v >= n) { ok = 0; break; }
        }
        g_is64 = ok;
    }
    if (blockIdx.x == 0 && tid < HID) { g_bn_sum[tid] = 0.f; g_bn_sq[tid] = 0.f; }
    for (int i = gid; i < n; i += gsz) g_deg[i] = 1;

    gridbar(&s_base, 1);

    // phase 1: degree count
    int is64 = g_is64;
    for (int e = gid; e < E; e += gsz) {
        int d = edge_at(ei, (long long)E + e, is64);
        atomicAdd(&g_deg[d], 1);
    }

    gridbar(&s_base, 2);

    // phase 2: exclusive scan (block 0 only)
    if (blockIdx.x == 0) {
        int c = (n + 1023) >> 10;
        int lo = tid * c;
        int hi = lo + c; if (hi > n) hi = n; if (lo > n) lo = n;
        int s = 0;
        for (int i = lo; i < hi; i++) s += g_deg[i];
        part[tid] = s;
        __syncthreads();
        for (int off = 1; off < 1024; off <<= 1) {
            int v = (tid >= off) ? part[tid - off] : 0;
            __syncthreads();
            part[tid] += v;
            __syncthreads();
        }
        int run = (tid > 0) ? part[tid - 1] : 0;
        for (int i = lo; i < hi; i++) {
            g_rowptr[i] = run;
            g_cursor[i] = run;
            run += g_deg[i];
        }
        if (tid == 1023) g_rowptr[n] = part[1023];
    }

    gridbar(&s_base, 3);

    // phase 3: scatter fill
    int total = E + n;
    for (int e = gid; e < total; e += gsz) {
        int s, d;
        if (e < E) {
            s = edge_at(ei, e, is64);
            d = edge_at(ei, (long long)E + e, is64);
        } else {
            s = d = e - E;
        }
        int pos = atomicAdd(&g_cursor[d], 1);
        g_csrc[pos] = s;
    }
}

// --- SGEMM + fused scores: h = f(A)*B stored fp16x2; esrc/edst from accs ---
template <bool TRANSFORM>
__global__ __launch_bounds__(256) void k_gemm128(const float* __restrict__ A,
                                                 const float* __restrict__ B,
                                                 const float* __restrict__ a_s,
                                                 const float* __restrict__ a_d,
                                                 int n) {
    __shared__ float As[16][128];  // [k][m]
    __shared__ float Bs[16][128];  // [k][col]
    int tid = threadIdx.x;
    int tx = tid & 15, ty = tid >> 4;
    int row0 = blockIdx.x * 128;

    float acc[8][8];
#pragma unroll
    for (int i = 0; i < 8; i++)
#pragma unroll
        for (int j = 0; j < 8; j++) acc[i][j] = 0.f;

    for (int k0 = 0; k0 < 128; k0 += 16) {
#pragma unroll
        for (int q = 0; q < 2; q++) {
            int i = tid * 2 + q;
            int m = i >> 2;
            int kq = i & 3;
            int row = row0 + m;
            float4 v = make_float4(0.f, 0.f, 0.f, 0.f);
            if (row < n) v = ((const float4*)A)[(long long)row * 32 + (k0 >> 2) + kq];
            if (TRANSFORM) {
                float4 sc = ((const float4*)g_bn_scale)[(k0 >> 2) + kq];
                float4 sh = ((const float4*)g_bn_shift)[(k0 >> 2) + kq];
                float t;
                t = v.x * sc.x + sh.x; v.x = (t > 0.f) ? t : expm1f(t);
                t = v.y * sc.y + sh.y; v.y = (t > 0.f) ? t : expm1f(t);
                t = v.z * sc.z + sh.z; v.z = (t > 0.f) ? t : expm1f(t);
                t = v.w * sc.w + sh.w; v.w = (t > 0.f) ? t : expm1f(t);
            }
            As[kq * 4 + 0][m] = v.x;
            As[kq * 4 + 1][m] = v.y;
            As[kq * 4 + 2][m] = v.z;
            As[kq * 4 + 3][m] = v.w;
        }
#pragma unroll
        for (int q = 0; q < 2; q++) {
            int i = tid * 2 + q;
            int kk = i >> 5;
            int c4 = i & 31;
            ((float4*)Bs[kk])[c4] = ((const float4*)B)[(k0 + kk) * 32 + c4];
        }
        __syncthreads();
#pragma unroll
        for (int kk = 0; kk < 16; kk++) {
            float a[8], b[8];
            *(float4*)(a)     = *(const float4*)&As[kk][ty * 8];
            *(float4*)(a + 4) = *(const float4*)&As[kk][ty * 8 + 4];
            *(float4*)(b)     = *(const float4*)&Bs[kk][tx * 8];
            *(float4*)(b + 4) = *(const float4*)&Bs[kk][tx * 8 + 4];
#pragma unroll
            for (int i = 0; i < 8; i++)
#pragma unroll
                for (int j = 0; j < 8; j++) acc[i][j] += a[i] * b[j];
        }
        __syncthreads();
    }
    // write h as packed fp16x2 (row stride 64 u32 = 16 uint4)
#pragma unroll
    for (int i = 0; i < 8; i++) {
        int row = row0 + ty * 8 + i;
        if (row < n) {
            uint4 p;
            p.x = pk_h2(acc[i][0], acc[i][1]);
            p.y = pk_h2(acc[i][2], acc[i][3]);
            p.z = pk_h2(acc[i][4], acc[i][5]);
            p.w = pk_h2(acc[i][6], acc[i][7]);
            ((uint4*)g_hpk)[(long long)row * 16 + tx] = p;
        }
    }
    // fused attention scores from exact fp32 accumulators
    float as_[8], ad_[8];
    *(float4*)(as_)     = ((const float4*)a_s)[tx * 2];
    *(float4*)(as_ + 4) = ((const float4*)a_s)[tx * 2 + 1];
    *(float4*)(ad_)     = ((const float4*)a_d)[tx * 2];
    *(float4*)(ad_ + 4) = ((const float4*)a_d)[tx * 2 + 1];
#pragma unroll
    for (int i = 0; i < 8; i++) {
        float ps = 0.f, pd = 0.f;
#pragma unroll
        for (int j = 0; j < 8; j++) { ps += acc[i][j] * as_[j]; pd += acc[i][j] * ad_[j]; }
#pragma unroll
        for (int o = 8; o; o >>= 1) {
            ps += __shfl_xor_sync(0xffffffffu, ps, o);
            pd += __shfl_xor_sync(0xffffffffu, pd, o);
        }
        int row = row0 + ty * 8 + i;
        if (tx == 0 && row < n) { g_esrc[row] = ps; g_edst[row] = pd; }
    }
}

// ------- per-node softmax over incoming edges -> alpha per CSR slot --------
__global__ __launch_bounds__(256) void k_alpha(int n) {
    int gid = blockIdx.x * blockDim.x + threadIdx.x;
    int w = gid >> 5, lane = gid & 31;
    if (w >= n) return;
    int b0 = g_rowptr[w], b1 = g_rowptr[w + 1];
    float ed = g_edst[w];

    float m = -1e30f;
    for (int j = b0 + lane; j < b1; j += 32) {
        float t = g_esrc[g_csrc[j]] + ed;
        float e = (t > 0.f) ? t : NEG_SLOPE * t;
        m = fmaxf(m, e);
    }
#pragma unroll
    for (int o = 16; o; o >>= 1) m = fmaxf(m, __shfl_xor_sync(0xffffffffu, m, o));

    float dl = 0.f;
    for (int j = b0 + lane; j < b1; j += 32) {
        float t = g_esrc[g_csrc[j]] + ed;
        float e = (t > 0.f) ? t : NEG_SLOPE * t;
        dl += __expf(e - m);
    }
#pragma unroll
    for (int o = 16; o; o >>= 1) dl += __shfl_xor_sync(0xffffffffu, dl, o);
    float inv = 1.0f / dl;

    for (int j = b0 + lane; j < b1; j += 32) {
        float t = g_esrc[g_csrc[j]] + ed;
        float e = (t > 0.f) ? t : NEG_SLOPE * t;
        g_alpha[j] = __expf(e - m) * inv;
    }
}

// ---- gather from fp16x2 table: 64 threads/node, thread = 2 features -------
#define GAT_NB 2048
__global__ __launch_bounds__(256) void k_gather_h(const float* __restrict__ bias,
                                                  float* __restrict__ out, int n) {
    int t = threadIdx.x & 63;           // fp16x2 slot (features 2t, 2t+1)
    int sub = threadIdx.x >> 6;         // 0..3 node slot in block
    float2 bb = ((const float2*)bias)[t];
    float s0 = 0.f, s1 = 0.f, q0 = 0.f, q1 = 0.f;

    for (int w = blockIdx.x * 4 + sub; w < n; w += GAT_NB * 4) {
        int b0 = g_rowptr[w], b1 = g_rowptr[w + 1];
        float ax = 0.f, ay = 0.f;
        int j = b0;
        for (; j + 4 <= b1; j += 4) {
            int   n0 = g_csrc[j],     n1 = g_csrc[j + 1];
            int   n2 = g_csrc[j + 2], n3 = g_csrc[j + 3];
            float a0 = g_alpha[j],     a1 = g_alpha[j + 1];
            float a2 = g_alpha[j + 2], a3 = g_alpha[j + 3];
            unsigned u0 = g_hpk[(long long)n0 * 64 + t];
            unsigned u1 = g_hpk[(long long)n1 * 64 + t];
            unsigned u2 = g_hpk[(long long)n2 * 64 + t];
            unsigned u3 = g_hpk[(long long)n3 * 64 + t];
            float2 f0 = __half22float2(*(__half2*)&u0);
            float2 f1 = __half22float2(*(__half2*)&u1);
            float2 f2 = __half22float2(*(__half2*)&u2);
            float2 f3 = __half22float2(*(__half2*)&u3);
            ax += a0 * f0.x + a1 * f1.x + a2 * f2.x + a3 * f3.x;
            ay += a0 * f0.y + a1 * f1.y + a2 * f2.y + a3 * f3.y;
        }
        for (; j < b1; j++) {
            unsigned u = g_hpk[(long long)g_csrc[j] * 64 + t];
            float2 f = __half22float2(*(__half2*)&u);
            float a = g_alpha[j];
            ax += a * f.x; ay += a * f.y;
        }
        float ox = ax + bb.x, oy = ay + bb.y;
        ((float2*)out)[(long long)w * 64 + t] = make_float2(ox, oy);
        s0 += ox; s1 += oy; q0 += ox * ox; q1 += oy * oy;
    }
    atomicAdd(&g_bn_sum[2 * t], s0);
    atomicAdd(&g_bn_sum[2 * t + 1], s1);
    atomicAdd(&g_bn_sq[2 * t], q0);
    atomicAdd(&g_bn_sq[2 * t + 1], q1);
}

// -------- BN finalize: scale/shift; resets accumulators for next layer -----
__global__ void k_bn_final(const float* __restrict__ gamma, const float* __restrict__ beta,
                           float inv_n) {
    int f = threadIdx.x;
    if (f < HID) {
        float mu = g_bn_sum[f] * inv_n;
        float var = g_bn_sq[f] * inv_n - mu * mu;
        float rstd = rsqrtf(var + BN_EPS);
        float sc = rstd * gamma[f];
        g_bn_scale[f] = sc;
        g_bn_shift[f] = beta[f] - mu * sc;
        g_bn_sum[f] = 0.f;
        g_bn_sq[f] = 0.f;
    }
}

// ---------------- output GEMM: elu(bn(h)) @ [128 x 40] + bias --------------
__global__ __launch_bounds__(256) void k_outgemm(const float* __restrict__ h,
                                                 const float* __restrict__ Wout,
                                                 const float* __restrict__ bout,
                                                 float* __restrict__ out, int n) {
    __shared__ float hs[32][129];
    __shared__ float ws[128 * NCLS];
    int r0 = blockIdx.x * 32;
    for (int i = threadIdx.x; i < 128 * NCLS; i += 256) ws[i] = Wout[i];
    for (int i = threadIdx.x; i < 32 * 128; i += 256) {
        int r = i >> 7, k = i & 127;
        float v = (r0 + r < n) ? h[(long long)(r0 + r) * 128 + k] : 0.f;
        float t = v * g_bn_scale[k] + g_bn_shift[k];
        hs[r][k] = (t > 0.f) ? t : expm1f(t);
    }
    __syncthreads();
    int r = threadIdx.x >> 3;
    int cg = threadIdx.x & 7;
    float acc[5] = {0.f, 0.f, 0.f, 0.f, 0.f};
    for (int k = 0; k < 128; k++) {
        float a = hs[r][k];
#pragma unroll
        for (int j = 0; j < 5; j++) acc[j] += a * ws[k * NCLS + cg * 5 + j];
    }
    int row = r0 + r;
    if (row < n) {
#pragma unroll
        for (int j = 0; j < 5; j++)
            out[(long long)row * NCLS + cg * 5 + j] = acc[j] + bout[cg * 5 + j];
    }
}

// ---------------- launch ----------------
extern "C" void kernel_launch(void* const* d_in, const int* in_sizes, int n_in,
                              void* d_out, int out_size) {
    const float* x    = (const float*)d_in[0];
    const void*  ei   = d_in[1];
    const float* W1   = (const float*)d_in[2];
    const float* as1  = (const float*)d_in[3];
    const float* ad1  = (const float*)d_in[4];
    const float* b1   = (const float*)d_in[5];
    const float* W2   = (const float*)d_in[6];
    const float* as2  = (const float*)d_in[7];
    const float* ad2  = (const float*)d_in[8];
    const float* b2   = (const float*)d_in[9];
    const float* gamma= (const float*)d_in[10];
    const float* beta = (const float*)d_in[11];
    const float* Wout = (const float*)d_in[12];
    const float* bout = (const float*)d_in[13];
    float* out = (float*)d_out;

    int n = in_sizes[0] / HID;       // 100000
    int E = in_sizes[1] / 2;         // 1600000
    float inv_n = 1.0f / (float)n;

    int gemm_blocks = (n + 127) / 128;
    int warp_blocks = (n + 7) / 8;

    // launch order (ncu profiles idx 3 -> k_gather_h):
    k_csr<<<CSR_NB, 1024>>>(ei, E, n);                                      // 0
    k_gemm128<false><<<gemm_blocks, 256>>>(x, W1, as1, ad1, n);             // 1
    k_alpha<<<warp_blocks, 256>>>(n);                                       // 2
    k_gather_h<<<GAT_NB, 256>>>(b1, g_bufB, n);                             // 3 <- ncu
    k_bn_final<<<1, HID>>>(gamma, beta, inv_n);                             // 4

    // --- layer 2 (BN+ELU fused into A-load of GEMM) ---
    k_gemm128<true><<<gemm_blocks, 256>>>(g_bufB, W2, as2, ad2, n);         // 5
    k_alpha<<<warp_blocks, 256>>>(n);                                       // 6
    k_gather_h<<<GAT_NB, 256>>>(b2, g_bufB, n);                             // 7
    k_bn_final<<<1, HID>>>(gamma, beta, inv_n);                             // 8

    // --- output projection (BN+ELU fused into h-load) ---
    k_outgemm<<<(n + 31) / 32, 256>>>(g_bufB, Wout, bout, out, n);          // 9
}